// round 6
// baseline (speedup 1.0000x reference)
#include <cuda_runtime.h>
#include <cuda_fp16.h>
#include <cstdint>

// Problem dims (fixed)
#define O_DIM 2048
#define I_DIM 2048
#define M_DIM 4096
#define KC    256
#define PQD   8

// Scratch (device globals: allocation-free rule)
__device__ __align__(16) __half g_wq[O_DIM * I_DIM];  // quantized weight fp16 [O][I]
__device__ __align__(16) __half g_x [M_DIM * I_DIM];  // x fp16 [M][K]

// ===========================================================================
// helpers
// ===========================================================================
__device__ __forceinline__ uint64_t ffma2(uint64_t a, uint64_t b, uint64_t c) {
    uint64_t d;
    asm("fma.rn.f32x2 %0, %1, %2, %3;" : "=l"(d) : "l"(a), "l"(b), "l"(c));
    return d;
}
__device__ __forceinline__ uint64_t pack2(float lo, float hi) {
    uint64_t d; asm("mov.b64 %0, {%1, %2};" : "=l"(d) : "f"(lo), "f"(hi)); return d;
}
__device__ __forceinline__ void unpack2(uint64_t v, float& lo, float& hi) {
    asm("mov.b64 {%0, %1}, %2;" : "=f"(lo), "=f"(hi) : "l"(v));
}
__device__ __forceinline__ void cp_async16(uint32_t s, const void* g) {
    asm volatile("cp.async.cg.shared.global [%0], [%1], 16;" :: "r"(s), "l"(g) : "memory");
}

// ===========================================================================
// Kernel 1 (fused): blocks [0,512)   -> PQ quantize weight -> g_wq (fp16)
//                   blocks [512,4608)-> convert x fp32 -> g_x fp16
// ===========================================================================
#define QBLOCKS 512

__global__ __launch_bounds__(256) void prep_kernel(const float* __restrict__ x,
                                                   const float* __restrict__ w,
                                                   const float* __restrict__ cb,
                                                   const float* __restrict__ rs) {
    int tid = threadIdx.x;
    if (blockIdx.x >= QBLOCKS) {
        // ---- convert x ----
        size_t i = ((size_t)(blockIdx.x - QBLOCKS) * 256 + tid) * 8;
        float4 a = *reinterpret_cast<const float4*>(x + i);
        float4 b = *reinterpret_cast<const float4*>(x + i + 4);
        __half2 h0 = __floats2half2_rn(a.x, a.y);
        __half2 h1 = __floats2half2_rn(a.z, a.w);
        __half2 h2 = __floats2half2_rn(b.x, b.y);
        __half2 h3 = __floats2half2_rn(b.z, b.w);
        uint4 v;
        v.x = *reinterpret_cast<uint32_t*>(&h0);
        v.y = *reinterpret_cast<uint32_t*>(&h1);
        v.z = *reinterpret_cast<uint32_t*>(&h2);
        v.w = *reinterpret_cast<uint32_t*>(&h3);
        *reinterpret_cast<uint4*>(g_x + i) = v;
        return;
    }

    // ---- quantize: 4 groups per thread, packed f32x2 scoring ----
    __shared__ __align__(16) float2 scb2[KC][10];
    {
        const float4* cb4 = reinterpret_cast<const float4*>(cb);
        float4 a = cb4[tid * 2];
        float4 b = cb4[tid * 2 + 1];
        float s = a.x * a.x;
        s = fmaf(a.y, a.y, s); s = fmaf(a.z, a.z, s); s = fmaf(a.w, a.w, s);
        s = fmaf(b.x, b.x, s); s = fmaf(b.y, b.y, s); s = fmaf(b.z, b.z, s); s = fmaf(b.w, b.w, s);
        float c2h = 0.5f * s;
        scb2[tid][0] = make_float2(a.x, a.x);
        scb2[tid][1] = make_float2(a.y, a.y);
        scb2[tid][2] = make_float2(a.z, a.z);
        scb2[tid][3] = make_float2(a.w, a.w);
        scb2[tid][4] = make_float2(b.x, b.x);
        scb2[tid][5] = make_float2(b.y, b.y);
        scb2[tid][6] = make_float2(b.z, b.z);
        scb2[tid][7] = make_float2(b.w, b.w);
        scb2[tid][8] = make_float2(c2h, c2h);
    }
    __syncthreads();

    uint32_t scb_s = (uint32_t)__cvta_generic_to_shared(&scb2[0][0]);

    int t4 = blockIdx.x * 256 + tid;     // 0..131071
    int g0 = t4 * 4;                     // 4 groups, all within one weight row
    float scale = rs[g0 >> 8];           // 256 groups per row
    float inv = 1.0f / scale;

    float xv[32];
    {
        const float4* wp = reinterpret_cast<const float4*>(w + (size_t)g0 * PQD);
#pragma unroll
        for (int q = 0; q < 8; q++) {
            float4 v = wp[q];
            xv[q * 4 + 0] = v.x; xv[q * 4 + 1] = v.y;
            xv[q * 4 + 2] = v.z; xv[q * 4 + 3] = v.w;
        }
    }
    uint64_t P01[8], P23[8];
#pragma unroll
    for (int j = 0; j < 8; j++) {
        P01[j] = pack2(-(xv[j] * inv), -(xv[8 + j] * inv));
        P23[j] = pack2(-(xv[16 + j] * inv), -(xv[24 + j] * inv));
    }

    float b0 = 3.4e38f, b1 = 3.4e38f, b2 = 3.4e38f, b3 = 3.4e38f;
    int i0 = 0, i1 = 0, i2 = 0, i3 = 0;

#pragma unroll 4
    for (int k = 0; k < KC; k++) {
        uint32_t a = scb_s + (uint32_t)k * 80;
        uint64_t c0, c1, c2, c3, c4, c5, c6, c7, ch;
        asm("ld.shared.v2.u64 {%0,%1}, [%2];" : "=l"(c0), "=l"(c1) : "r"(a));
        asm("ld.shared.v2.u64 {%0,%1}, [%2];" : "=l"(c2), "=l"(c3) : "r"(a + 16));
        asm("ld.shared.v2.u64 {%0,%1}, [%2];" : "=l"(c4), "=l"(c5) : "r"(a + 32));
        asm("ld.shared.v2.u64 {%0,%1}, [%2];" : "=l"(c6), "=l"(c7) : "r"(a + 48));
        asm("ld.shared.b64 %0, [%1];" : "=l"(ch) : "r"(a + 64));
        uint64_t d01 = ch, d23 = ch;
        d01 = ffma2(P01[0], c0, d01); d23 = ffma2(P23[0], c0, d23);
        d01 = ffma2(P01[1], c1, d01); d23 = ffma2(P23[1], c1, d23);
        d01 = ffma2(P01[2], c2, d01); d23 = ffma2(P23[2], c2, d23);
        d01 = ffma2(P01[3], c3, d01); d23 = ffma2(P23[3], c3, d23);
        d01 = ffma2(P01[4], c4, d01); d23 = ffma2(P23[4], c4, d23);
        d01 = ffma2(P01[5], c5, d01); d23 = ffma2(P23[5], c5, d23);
        d01 = ffma2(P01[6], c6, d01); d23 = ffma2(P23[6], c6, d23);
        d01 = ffma2(P01[7], c7, d01); d23 = ffma2(P23[7], c7, d23);
        float s0, s1, s2, s3;
        unpack2(d01, s0, s1);
        unpack2(d23, s2, s3);
        if (s0 < b0) { b0 = s0; i0 = k; }
        if (s1 < b1) { b1 = s1; i1 = k; }
        if (s2 < b2) { b2 = s2; i2 = k; }
        if (s3 < b3) { b3 = s3; i3 = k; }
    }

    int idxs[4] = {i0, i1, i2, i3};
#pragma unroll
    for (int g = 0; g < 4; g++) {
        int bi = idxs[g];
        __half2 h[4];
#pragma unroll
        for (int j = 0; j < 4; j++) {
            float lo = scb2[bi][2 * j].x * scale;
            float hi = scb2[bi][2 * j + 1].x * scale;
            h[j] = __floats2half2_rn(lo, hi);
        }
        uint4 v;
        v.x = *reinterpret_cast<uint32_t*>(&h[0]);
        v.y = *reinterpret_cast<uint32_t*>(&h[1]);
        v.z = *reinterpret_cast<uint32_t*>(&h[2]);
        v.w = *reinterpret_cast<uint32_t*>(&h[3]);
        *reinterpret_cast<uint4*>(g_wq + (size_t)(g0 + g) * PQD) = v;
    }
}

// ===========================================================================
// Kernel 2: GEMM  out[M,N] = g_x[M,K] @ g_wq[N,K]^T + bias  (mma.sync fp16/f32)
//   128M x 128N x 32K block, 8 warps @ 32x64, 4-stage cp.async ring,
//   2 CTAs/SM (latency hiding — R5 showed occ 12.4%, tensor 33.7%).
// ===========================================================================
#define GBM 128
#define GBN 128
#define GBK 32
#define LDSW 40                         // halves per smem row (32 + 8 pad)
#define A_BYTES (GBM * LDSW * 2)        // 10240
#define B_BYTES (GBN * LDSW * 2)        // 10240
#define STG_BYTES (A_BYTES + B_BYTES)   // 20480
#define NSTG 4
#define GSMEM (NSTG * STG_BYTES)        // 81920

__global__ __launch_bounds__(256, 2) void gemm_kernel(const float* __restrict__ bias,
                                                      float* __restrict__ out) {
    extern __shared__ char smem_raw[];
    uint32_t sb = (uint32_t)__cvta_generic_to_shared(smem_raw);

    int tid  = threadIdx.x;
    int lane = tid & 31;
    int wid  = tid >> 5;
    int bm0  = blockIdx.y * GBM;
    int bn0  = blockIdx.x * GBN;
    int wm   = (wid >> 1) * 32;      // 4 warps in M
    int wn   = (wid & 1) * 64;       // 2 warps in N

    // loader mapping: each thread loads 2x16B for A and 2x16B for B
    int lrow = tid >> 1;             // 0..127
    int lcol = (tid & 1) * 16;       // halves: 0 or 16
    const __half* gAp = g_x  + (size_t)(bm0 + lrow) * I_DIM + lcol;
    const __half* gBp = g_wq + (size_t)(bn0 + lrow) * I_DIM + lcol;
    uint32_t sa_off = (uint32_t)((lrow * LDSW + lcol) * 2);
    uint32_t sb_off = (uint32_t)(A_BYTES + (lrow * LDSW + lcol) * 2);

#define G_LOAD(slot, k0)                                                     \
    do {                                                                     \
        uint32_t bse = sb + (uint32_t)(slot) * STG_BYTES;                    \
        cp_async16(bse + sa_off,      gAp + (k0));                           \
        cp_async16(bse + sa_off + 16, gAp + (k0) + 8);                       \
        cp_async16(bse + sb_off,      gBp + (k0));                           \
        cp_async16(bse + sb_off + 16, gBp + (k0) + 8);                       \
        asm volatile("cp.async.commit_group;" ::: "memory");                 \
    } while (0)

    float acc[2][8][4];
#pragma unroll
    for (int mi = 0; mi < 2; mi++)
#pragma unroll
        for (int ni = 0; ni < 8; ni++)
#pragma unroll
            for (int r = 0; r < 4; r++) acc[mi][ni][r] = 0.0f;

    // prologue: stages 0..2
    G_LOAD(0, 0);
    G_LOAD(1, GBK);
    G_LOAD(2, 2 * GBK);

    uint32_t a_frag_off = (uint32_t)(((wm + (lane & 15)) * LDSW + (lane >> 4) * 8) * 2);
    uint32_t b_frag_off = (uint32_t)(A_BYTES +
        ((wn + (lane & 7) + ((lane >> 4) & 1) * 8) * LDSW + ((lane >> 3) & 1) * 8) * 2);

    const int KT = I_DIM / GBK;  // 64
    for (int kt = 0; kt < KT; kt++) {
        asm volatile("cp.async.wait_group 2;" ::: "memory");
        __syncthreads();
        if (kt + 3 < KT) {
            G_LOAD((kt + 3) & 3, (kt + 3) * GBK);
        } else {
            asm volatile("cp.async.commit_group;" ::: "memory");
        }

        uint32_t stg = sb + (uint32_t)(kt & 3) * STG_BYTES;
        uint32_t aBase = stg + a_frag_off;
        uint32_t bBase = stg + b_frag_off;

#pragma unroll
        for (int ks = 0; ks < 2; ks++) {
            uint32_t a[2][4], b[8][2];
#pragma unroll
            for (int mi = 0; mi < 2; mi++) {
                uint32_t addr = aBase + (uint32_t)((mi * 16 * LDSW + ks * 16) * 2);
                asm volatile("ldmatrix.sync.aligned.m8n8.x4.shared.b16 {%0,%1,%2,%3}, [%4];"
                             : "=r"(a[mi][0]), "=r"(a[mi][1]), "=r"(a[mi][2]), "=r"(a[mi][3])
                             : "r"(addr));
            }
#pragma unroll
            for (int p = 0; p < 4; p++) {
                uint32_t addr = bBase + (uint32_t)((p * 16 * LDSW + ks * 16) * 2);
                asm volatile("ldmatrix.sync.aligned.m8n8.x4.shared.b16 {%0,%1,%2,%3}, [%4];"
                             : "=r"(b[2 * p][0]), "=r"(b[2 * p][1]),
                               "=r"(b[2 * p + 1][0]), "=r"(b[2 * p + 1][1])
                             : "r"(addr));
            }
#pragma unroll
            for (int mi = 0; mi < 2; mi++)
#pragma unroll
                for (int ni = 0; ni < 8; ni++) {
                    asm volatile(
                        "mma.sync.aligned.m16n8k16.row.col.f32.f16.f16.f32 "
                        "{%0,%1,%2,%3}, {%4,%5,%6,%7}, {%8,%9}, {%0,%1,%2,%3};"
                        : "+f"(acc[mi][ni][0]), "+f"(acc[mi][ni][1]),
                          "+f"(acc[mi][ni][2]), "+f"(acc[mi][ni][3])
                        : "r"(a[mi][0]), "r"(a[mi][1]), "r"(a[mi][2]), "r"(a[mi][3]),
                          "r"(b[ni][0]), "r"(b[ni][1]));
                }
        }
    }

    // epilogue: += bias, fp32 store
#pragma unroll
    for (int mi = 0; mi < 2; mi++) {
        int row = bm0 + wm + mi * 16 + (lane >> 2);
        float* o0 = out + (size_t)row * O_DIM;
        float* o1 = out + (size_t)(row + 8) * O_DIM;
#pragma unroll
        for (int ni = 0; ni < 8; ni++) {
            int col = bn0 + wn + ni * 8 + (lane & 3) * 2;
            float bv0 = bias[col];
            float bv1 = bias[col + 1];
            *reinterpret_cast<float2*>(o0 + col) =
                make_float2(acc[mi][ni][0] + bv0, acc[mi][ni][1] + bv1);
            *reinterpret_cast<float2*>(o1 + col) =
                make_float2(acc[mi][ni][2] + bv0, acc[mi][ni][3] + bv1);
        }
    }
}

// ===========================================================================
extern "C" void kernel_launch(void* const* d_in, const int* in_sizes, int n_in,
                              void* d_out, int out_size) {
    const float* x    = (const float*)d_in[0];
    const float* w    = (const float*)d_in[1];
    const float* cb   = (const float*)d_in[2];
    const float* rs   = (const float*)d_in[3];
    const float* bias = (const float*)d_in[4];
    float* out = (float*)d_out;

    static bool attr_done = false;
    if (!attr_done) {
        cudaFuncSetAttribute(gemm_kernel, cudaFuncAttributeMaxDynamicSharedMemorySize, GSMEM);
        attr_done = true;
    }

    prep_kernel<<<QBLOCKS + M_DIM * I_DIM / (256 * 8), 256>>>(x, w, cb, rs);
    dim3 grid(O_DIM / GBN, M_DIM / GBM);
    gemm_kernel<<<grid, 256, GSMEM>>>(bias, out);
}

// round 7
// speedup vs baseline: 1.4047x; 1.4047x over previous
#include <cuda_runtime.h>
#include <cuda_fp16.h>
#include <cstdint>

// Problem dims (fixed)
#define O_DIM 2048
#define I_DIM 2048
#define M_DIM 4096
#define KC    256
#define PQD   8

// Tiled-swizzled scratch layout:
//   [tile128][kstage(64 halves)][128 rows x 128 bytes, SW128-swizzled] = 16KB blocks
//   tile stride = 32 stages * 16KB = 512KB
#define KSB      16384
#define TILE_STR (32 * KSB)

__device__ __align__(16) char g_wq[O_DIM * I_DIM * 2];  // fp16, tiled-swizzled
__device__ __align__(16) char g_x [M_DIM * I_DIM * 2];  // fp16, tiled-swizzled

__device__ __forceinline__ void cp_async16(uint32_t s, const void* g) {
    asm volatile("cp.async.cg.shared.global [%0], [%1], 16;" :: "r"(s), "l"(g) : "memory");
}
// byte offset of (row r in 0..127, half-col c in 0..63) inside a 16KB block
__device__ __forceinline__ uint32_t tile_off(int r, int ch) {
    // ch = byte col (0..127), 16B aligned. SW128: c ^= (r&7)<<4
    return (uint32_t)(r * 128 + (ch ^ ((r & 7) << 4)));
}

// ===========================================================================
// Kernel 1 (fused): blocks [0,2048)    -> PQ quantize -> g_wq (tiled)
//                   blocks [2048,6144) -> convert x   -> g_x  (tiled)
// ===========================================================================
#define QBLOCKS 2048

__global__ __launch_bounds__(256) void prep_kernel(const float* __restrict__ x,
                                                   const float* __restrict__ w,
                                                   const float* __restrict__ cb,
                                                   const float* __restrict__ rs) {
    int tid = threadIdx.x;
    if (blockIdx.x >= QBLOCKS) {
        // ---- convert x: 8 floats -> one 16B chunk in tiled layout ----
        int g = (blockIdx.x - QBLOCKS) * 256 + tid;
        int m = g >> 8;               // row
        int i = (g & 255) * 8;        // half-col
        size_t src = (size_t)m * I_DIM + i;
        float4 a = *reinterpret_cast<const float4*>(x + src);
        float4 b = *reinterpret_cast<const float4*>(x + src + 4);
        __half2 h0 = __floats2half2_rn(a.x, a.y);
        __half2 h1 = __floats2half2_rn(a.z, a.w);
        __half2 h2 = __floats2half2_rn(b.x, b.y);
        __half2 h3 = __floats2half2_rn(b.z, b.w);
        uint4 v;
        v.x = *reinterpret_cast<uint32_t*>(&h0);
        v.y = *reinterpret_cast<uint32_t*>(&h1);
        v.z = *reinterpret_cast<uint32_t*>(&h2);
        v.w = *reinterpret_cast<uint32_t*>(&h3);
        size_t dst = (size_t)(m >> 7) * TILE_STR + (size_t)(i >> 6) * KSB
                   + tile_off(m & 127, (i & 63) * 2);
        *reinterpret_cast<uint4*>(g_x + dst) = v;
        return;
    }

    // ---- quantize: 1 group per thread (R1 structure) ----
    __shared__ float4 scb[KC][2];
    __shared__ float  sc2[KC];
    {
        const float4* cb4 = reinterpret_cast<const float4*>(cb);
        float4 a = cb4[tid * 2];
        float4 b = cb4[tid * 2 + 1];
        scb[tid][0] = a;
        scb[tid][1] = b;
        float s = a.x * a.x;
        s = fmaf(a.y, a.y, s); s = fmaf(a.z, a.z, s); s = fmaf(a.w, a.w, s);
        s = fmaf(b.x, b.x, s); s = fmaf(b.y, b.y, s); s = fmaf(b.z, b.z, s); s = fmaf(b.w, b.w, s);
        sc2[tid] = s;
    }
    __syncthreads();

    int g    = blockIdx.x * 256 + tid;
    int flat = g * PQD;
    float scale = rs[flat >> 11];

    float4 wa = *reinterpret_cast<const float4*>(w + flat);
    float4 wb = *reinterpret_cast<const float4*>(w + flat + 4);
    float x0 = wa.x / scale, x1 = wa.y / scale, x2 = wa.z / scale, x3 = wa.w / scale;
    float x4 = wb.x / scale, x5 = wb.y / scale, x6 = wb.z / scale, x7 = wb.w / scale;

    float xs = x0 * x0;
    xs = fmaf(x1, x1, xs); xs = fmaf(x2, x2, xs); xs = fmaf(x3, x3, xs);
    xs = fmaf(x4, x4, xs); xs = fmaf(x5, x5, xs); xs = fmaf(x6, x6, xs); xs = fmaf(x7, x7, xs);

    float best = 3.4e38f;
    int   bi   = 0;
#pragma unroll 4
    for (int k = 0; k < KC; k++) {
        float4 ca = scb[k][0];
        float4 cv = scb[k][1];
        float dot = x0 * ca.x;
        dot = fmaf(x1, ca.y, dot); dot = fmaf(x2, ca.z, dot); dot = fmaf(x3, ca.w, dot);
        dot = fmaf(x4, cv.x, dot); dot = fmaf(x5, cv.y, dot); dot = fmaf(x6, cv.z, dot); dot = fmaf(x7, cv.w, dot);
        float d2 = __fadd_rn(__fsub_rn(xs, __fmul_rn(2.0f, dot)), sc2[k]);
        if (d2 < best) { best = d2; bi = k; }
    }

    float4 qa = scb[bi][0];
    float4 qb = scb[bi][1];
    __half2 h0 = __floats2half2_rn(qa.x * scale, qa.y * scale);
    __half2 h1 = __floats2half2_rn(qa.z * scale, qa.w * scale);
    __half2 h2 = __floats2half2_rn(qb.x * scale, qb.y * scale);
    __half2 h3 = __floats2half2_rn(qb.z * scale, qb.w * scale);
    uint4 v;
    v.x = *reinterpret_cast<uint32_t*>(&h0);
    v.y = *reinterpret_cast<uint32_t*>(&h1);
    v.z = *reinterpret_cast<uint32_t*>(&h2);
    v.w = *reinterpret_cast<uint32_t*>(&h3);
    int o = g >> 8;            // output row
    int i = (g & 255) * 8;     // half-col
    size_t dst = (size_t)(o >> 7) * TILE_STR + (size_t)(i >> 6) * KSB
               + tile_off(o & 127, (i & 63) * 2);
    *reinterpret_cast<uint4*>(g_wq + dst) = v;
}

// ===========================================================================
// Kernel 2: GEMM  out = x @ wq^T + bias  (mma.sync fp16/f32)
//   128M x 256N x 64K block, 8 warps @ 64x64, 3-stage ring,
//   contiguous pre-swizzled stage copies (4-line coalesced cp.async).
// ===========================================================================
#define GBM 128
#define GBN 256
#define KTILES 32                       // 2048 / 64
#define A_ST 16384                      // one 128x64h block
#define B_ST 32768                      // two 128x64h blocks
#define STAGE (A_ST + B_ST)             // 49152
#define NSTG 3
#define GSMEM (NSTG * STAGE)            // 147456

__global__ __launch_bounds__(256, 1) void gemm_kernel(const float* __restrict__ bias,
                                                      float* __restrict__ out) {
    extern __shared__ char smem_raw[];
    uint32_t sb = (uint32_t)__cvta_generic_to_shared(smem_raw);

    int tid  = threadIdx.x;
    int lane = tid & 31;
    int wid  = tid >> 5;
    int bm0  = blockIdx.y * GBM;
    int bn0  = blockIdx.x * GBN;
    int wm   = (wid >> 2) * 64;      // 2 warps in M
    int wn   = (wid & 3) * 64;       // 4 warps in N

    // ---- contiguous loaders ----
    // A: 16KB stage -> thread copies bytes [tid*64, tid*64+64)
    // B: 32KB stage -> thread copies bytes [tid*128, tid*128+128)
    const char* srcA = g_x  + (size_t)blockIdx.y * TILE_STR + (size_t)tid * 64;
    int bblk = (tid * 128) >> 14;    // 0 or 1 (n-subtile)
    int boff = (tid * 128) & 16383;
    const char* srcB = g_wq + (size_t)(blockIdx.x * 2 + bblk) * TILE_STR + boff;
    uint32_t dstA = (uint32_t)(tid * 64);
    uint32_t dstB = (uint32_t)(A_ST + tid * 128);

#define G_LOAD(slot, s)                                                       \
    do {                                                                      \
        uint32_t bse = sb + (uint32_t)(slot) * STAGE;                         \
        const char* pa = srcA + (size_t)(s) * KSB;                            \
        const char* pb = srcB + (size_t)(s) * KSB;                            \
        cp_async16(bse + dstA,      pa);                                      \
        cp_async16(bse + dstA + 16, pa + 16);                                 \
        cp_async16(bse + dstA + 32, pa + 32);                                 \
        cp_async16(bse + dstA + 48, pa + 48);                                 \
        cp_async16(bse + dstB,       pb);                                     \
        cp_async16(bse + dstB + 16,  pb + 16);                                \
        cp_async16(bse + dstB + 32,  pb + 32);                                \
        cp_async16(bse + dstB + 48,  pb + 48);                                \
        cp_async16(bse + dstB + 64,  pb + 64);                                \
        cp_async16(bse + dstB + 80,  pb + 80);                                \
        cp_async16(bse + dstB + 96,  pb + 96);                                \
        cp_async16(bse + dstB + 112, pb + 112);                               \
        asm volatile("cp.async.commit_group;" ::: "memory");                  \
    } while (0)

    // ---- ldmatrix per-lane bases (swizzle baked in) ----
    // A: row = wm + mi*16 + (lane&15); chunk = (lane>>4)*16
    uint32_t aRB[4], aXOR[4];
#pragma unroll
    for (int mi = 0; mi < 4; mi++) {
        int row = wm + mi * 16 + (lane & 15);
        aRB[mi]  = (uint32_t)(row * 128);
        aXOR[mi] = (uint32_t)((row & 7) << 4);
    }
    uint32_t aCH = (uint32_t)((lane >> 4) * 16);
    // B: row = wn + (lane&7) + ((lane>>4)&1)*8 + p*16; chunk = ((lane>>3)&1)*16
    uint32_t bRB[4], bXOR[4];
#pragma unroll
    for (int p = 0; p < 4; p++) {
        int row = wn + (lane & 7) + ((lane >> 4) & 1) * 8 + p * 16;
        bRB[p]  = (uint32_t)(A_ST + (row >> 7) * KSB + (row & 127) * 128);
        bXOR[p] = (uint32_t)((row & 7) << 4);
    }
    uint32_t bCH = (uint32_t)(((lane >> 3) & 1) * 16);

    float acc[4][8][4];
#pragma unroll
    for (int mi = 0; mi < 4; mi++)
#pragma unroll
        for (int ni = 0; ni < 8; ni++)
#pragma unroll
            for (int r = 0; r < 4; r++) acc[mi][ni][r] = 0.0f;

    // prologue
    G_LOAD(0, 0);
    G_LOAD(1, 1);

    int slot = 0, wslot = 2;
    for (int kt = 0; kt < KTILES; kt++) {
        asm volatile("cp.async.wait_group 1;" ::: "memory");
        __syncthreads();
        if (kt + 2 < KTILES) {
            G_LOAD(wslot, kt + 2);
        } else {
            asm volatile("cp.async.commit_group;" ::: "memory");
        }

        uint32_t stg = sb + (uint32_t)slot * STAGE;

#pragma unroll
        for (int ks = 0; ks < 4; ks++) {
            uint32_t kb = (uint32_t)(ks * 32);
            uint32_t a[4][4], b[8][2];
#pragma unroll
            for (int mi = 0; mi < 4; mi++) {
                uint32_t addr = stg + aRB[mi] + (((kb + aCH) ^ aXOR[mi]));
                asm volatile("ldmatrix.sync.aligned.m8n8.x4.shared.b16 {%0,%1,%2,%3}, [%4];"
                             : "=r"(a[mi][0]), "=r"(a[mi][1]), "=r"(a[mi][2]), "=r"(a[mi][3])
                             : "r"(addr));
            }
#pragma unroll
            for (int p = 0; p < 4; p++) {
                uint32_t addr = stg + bRB[p] + (((kb + bCH) ^ bXOR[p]));
                asm volatile("ldmatrix.sync.aligned.m8n8.x4.shared.b16 {%0,%1,%2,%3}, [%4];"
                             : "=r"(b[2 * p][0]), "=r"(b[2 * p][1]),
                               "=r"(b[2 * p + 1][0]), "=r"(b[2 * p + 1][1])
                             : "r"(addr));
            }
#pragma unroll
            for (int mi = 0; mi < 4; mi++)
#pragma unroll
                for (int ni = 0; ni < 8; ni++) {
                    asm volatile(
                        "mma.sync.aligned.m16n8k16.row.col.f32.f16.f16.f32 "
                        "{%0,%1,%2,%3}, {%4,%5,%6,%7}, {%8,%9}, {%0,%1,%2,%3};"
                        : "+f"(acc[mi][ni][0]), "+f"(acc[mi][ni][1]),
                          "+f"(acc[mi][ni][2]), "+f"(acc[mi][ni][3])
                        : "r"(a[mi][0]), "r"(a[mi][1]), "r"(a[mi][2]), "r"(a[mi][3]),
                          "r"(b[ni][0]), "r"(b[ni][1]));
                }
        }
        slot  = (slot == 2)  ? 0 : slot + 1;
        wslot = (wslot == 2) ? 0 : wslot + 1;
    }

    // epilogue: += bias, fp32 store
#pragma unroll
    for (int mi = 0; mi < 4; mi++) {
        int row = bm0 + wm + mi * 16 + (lane >> 2);
        float* o0 = out + (size_t)row * O_DIM;
        float* o1 = out + (size_t)(row + 8) * O_DIM;
#pragma unroll
        for (int ni = 0; ni < 8; ni++) {
            int col = bn0 + wn + ni * 8 + (lane & 3) * 2;
            float bv0 = bias[col];
            float bv1 = bias[col + 1];
            *reinterpret_cast<float2*>(o0 + col) =
                make_float2(acc[mi][ni][0] + bv0, acc[mi][ni][1] + bv1);
            *reinterpret_cast<float2*>(o1 + col) =
                make_float2(acc[mi][ni][2] + bv0, acc[mi][ni][3] + bv1);
        }
    }
}

// ===========================================================================
extern "C" void kernel_launch(void* const* d_in, const int* in_sizes, int n_in,
                              void* d_out, int out_size) {
    const float* x    = (const float*)d_in[0];
    const float* w    = (const float*)d_in[1];
    const float* cb   = (const float*)d_in[2];
    const float* rs   = (const float*)d_in[3];
    const float* bias = (const float*)d_in[4];
    float* out = (float*)d_out;

    static bool attr_done = false;
    if (!attr_done) {
        cudaFuncSetAttribute(gemm_kernel, cudaFuncAttributeMaxDynamicSharedMemorySize, GSMEM);
        attr_done = true;
    }

    prep_kernel<<<QBLOCKS + M_DIM * I_DIM / (256 * 8), 256>>>(x, w, cb, rs);
    dim3 grid(O_DIM / GBN, M_DIM / GBM);
    gemm_kernel<<<grid, 256, GSMEM>>>(bias, out);
}

// round 8
// speedup vs baseline: 1.5521x; 1.1049x over previous
#include <cuda_runtime.h>
#include <cuda_fp16.h>
#include <cstdint>

// Problem dims (fixed)
#define O_DIM 2048
#define I_DIM 2048
#define M_DIM 4096
#define KC    256
#define PQD   8

// Tiled-swizzled scratch layout:
//   [tile128][kstage(64 halves)][128 rows x 128 bytes, SW128-swizzled] = 16KB blocks
#define KSB      16384
#define TILE_STR (32 * KSB)

__device__ __align__(16) char g_wq[O_DIM * I_DIM * 2];  // fp16, tiled-swizzled
__device__ __align__(16) char g_x [M_DIM * I_DIM * 2];  // fp16, tiled-swizzled

__device__ __forceinline__ void cp_async16(uint32_t s, const void* g) {
    asm volatile("cp.async.cg.shared.global [%0], [%1], 16;" :: "r"(s), "l"(g) : "memory");
}
__device__ __forceinline__ uint32_t tile_off(int r, int ch) {
    return (uint32_t)(r * 128 + (ch ^ ((r & 7) << 4)));
}
__device__ __forceinline__ uint64_t ffma2(uint64_t a, uint64_t b, uint64_t c) {
    uint64_t d;
    asm("fma.rn.f32x2 %0, %1, %2, %3;" : "=l"(d) : "l"(a), "l"(b), "l"(c));
    return d;
}
__device__ __forceinline__ uint64_t pack2(float lo, float hi) {
    uint64_t d; asm("mov.b64 %0, {%1, %2};" : "=l"(d) : "f"(lo), "f"(hi)); return d;
}
__device__ __forceinline__ void unpack2(uint64_t v, float& lo, float& hi) {
    asm("mov.b64 {%0, %1}, %2;" : "=f"(lo), "=f"(hi) : "l"(v));
}
__device__ __forceinline__ void ldsm_x4(uint32_t addr, uint32_t* r) {
    asm volatile("ldmatrix.sync.aligned.m8n8.x4.shared.b16 {%0,%1,%2,%3}, [%4];"
                 : "=r"(r[0]), "=r"(r[1]), "=r"(r[2]), "=r"(r[3]) : "r"(addr));
}

// ===========================================================================
// Kernel 1 (fused): blocks [0,512)    -> PQ quantize (f32x2, 4 groups/thread)
//                   blocks [512,4608) -> convert x fp32 -> fp16 tiled
// ===========================================================================
#define QBLOCKS 512

__global__ __launch_bounds__(256) void prep_kernel(const float* __restrict__ x,
                                                   const float* __restrict__ w,
                                                   const float* __restrict__ cb,
                                                   const float* __restrict__ rs) {
    int tid = threadIdx.x;
    if (blockIdx.x >= QBLOCKS) {
        // ---- convert x: 8 floats -> one 16B chunk in tiled layout ----
        int g = (blockIdx.x - QBLOCKS) * 256 + tid;
        int m = g >> 8;
        int i = (g & 255) * 8;
        size_t src = (size_t)m * I_DIM + i;
        float4 a = *reinterpret_cast<const float4*>(x + src);
        float4 b = *reinterpret_cast<const float4*>(x + src + 4);
        __half2 h0 = __floats2half2_rn(a.x, a.y);
        __half2 h1 = __floats2half2_rn(a.z, a.w);
        __half2 h2 = __floats2half2_rn(b.x, b.y);
        __half2 h3 = __floats2half2_rn(b.z, b.w);
        uint4 v;
        v.x = *reinterpret_cast<uint32_t*>(&h0);
        v.y = *reinterpret_cast<uint32_t*>(&h1);
        v.z = *reinterpret_cast<uint32_t*>(&h2);
        v.w = *reinterpret_cast<uint32_t*>(&h3);
        size_t dst = (size_t)(m >> 7) * TILE_STR + (size_t)(i >> 6) * KSB
                   + tile_off(m & 127, (i & 63) * 2);
        *reinterpret_cast<uint4*>(g_x + dst) = v;
        return;
    }

    // ---- quantize: 4 groups/thread, packed f32x2 scoring (s = c.x - c^2/2 form
    //      negated: d = c^2/2 - c.x, argmin d == argmin ||x-c||^2) ----
    __shared__ __align__(16) float2 scb2[KC][10];
    {
        const float4* cb4 = reinterpret_cast<const float4*>(cb);
        float4 a = cb4[tid * 2];
        float4 b = cb4[tid * 2 + 1];
        float s = a.x * a.x;
        s = fmaf(a.y, a.y, s); s = fmaf(a.z, a.z, s); s = fmaf(a.w, a.w, s);
        s = fmaf(b.x, b.x, s); s = fmaf(b.y, b.y, s); s = fmaf(b.z, b.z, s); s = fmaf(b.w, b.w, s);
        float c2h = 0.5f * s;
        scb2[tid][0] = make_float2(a.x, a.x);
        scb2[tid][1] = make_float2(a.y, a.y);
        scb2[tid][2] = make_float2(a.z, a.z);
        scb2[tid][3] = make_float2(a.w, a.w);
        scb2[tid][4] = make_float2(b.x, b.x);
        scb2[tid][5] = make_float2(b.y, b.y);
        scb2[tid][6] = make_float2(b.z, b.z);
        scb2[tid][7] = make_float2(b.w, b.w);
        scb2[tid][8] = make_float2(c2h, c2h);
    }
    __syncthreads();

    uint32_t scb_s = (uint32_t)__cvta_generic_to_shared(&scb2[0][0]);

    int t4 = blockIdx.x * 256 + tid;
    int g0 = t4 * 4;
    float scale = rs[g0 >> 8];
    float inv = 1.0f / scale;

    float xv[32];
    {
        const float4* wp = reinterpret_cast<const float4*>(w + (size_t)g0 * PQD);
#pragma unroll
        for (int q = 0; q < 8; q++) {
            float4 v = wp[q];
            xv[q * 4 + 0] = v.x; xv[q * 4 + 1] = v.y;
            xv[q * 4 + 2] = v.z; xv[q * 4 + 3] = v.w;
        }
    }
    uint64_t P01[8], P23[8];
#pragma unroll
    for (int j = 0; j < 8; j++) {
        P01[j] = pack2(-(xv[j] * inv), -(xv[8 + j] * inv));
        P23[j] = pack2(-(xv[16 + j] * inv), -(xv[24 + j] * inv));
    }

    float b0 = 3.4e38f, b1 = 3.4e38f, b2 = 3.4e38f, b3 = 3.4e38f;
    int i0 = 0, i1 = 0, i2 = 0, i3 = 0;

#pragma unroll 4
    for (int k = 0; k < KC; k++) {
        uint32_t a = scb_s + (uint32_t)k * 80;
        uint64_t c0, c1, c2, c3, c4, c5, c6, c7, ch;
        asm("ld.shared.v2.u64 {%0,%1}, [%2];" : "=l"(c0), "=l"(c1) : "r"(a));
        asm("ld.shared.v2.u64 {%0,%1}, [%2];" : "=l"(c2), "=l"(c3) : "r"(a + 16));
        asm("ld.shared.v2.u64 {%0,%1}, [%2];" : "=l"(c4), "=l"(c5) : "r"(a + 32));
        asm("ld.shared.v2.u64 {%0,%1}, [%2];" : "=l"(c6), "=l"(c7) : "r"(a + 48));
        asm("ld.shared.b64 %0, [%1];" : "=l"(ch) : "r"(a + 64));
        uint64_t d01 = ch, d23 = ch;
        d01 = ffma2(P01[0], c0, d01); d23 = ffma2(P23[0], c0, d23);
        d01 = ffma2(P01[1], c1, d01); d23 = ffma2(P23[1], c1, d23);
        d01 = ffma2(P01[2], c2, d01); d23 = ffma2(P23[2], c2, d23);
        d01 = ffma2(P01[3], c3, d01); d23 = ffma2(P23[3], c3, d23);
        d01 = ffma2(P01[4], c4, d01); d23 = ffma2(P23[4], c4, d23);
        d01 = ffma2(P01[5], c5, d01); d23 = ffma2(P23[5], c5, d23);
        d01 = ffma2(P01[6], c6, d01); d23 = ffma2(P23[6], c6, d23);
        d01 = ffma2(P01[7], c7, d01); d23 = ffma2(P23[7], c7, d23);
        float s0, s1, s2, s3;
        unpack2(d01, s0, s1);
        unpack2(d23, s2, s3);
        if (s0 < b0) { b0 = s0; i0 = k; }
        if (s1 < b1) { b1 = s1; i1 = k; }
        if (s2 < b2) { b2 = s2; i2 = k; }
        if (s3 < b3) { b3 = s3; i3 = k; }
    }

    int idxs[4] = {i0, i1, i2, i3};
    int o = g0 >> 8;
    int ibase = (g0 & 255) * 8;
    size_t rowbase = (size_t)(o >> 7) * TILE_STR;
    int rr = o & 127;
#pragma unroll
    for (int g = 0; g < 4; g++) {
        int bi = idxs[g];
        __half2 h[4];
#pragma unroll
        for (int j = 0; j < 4; j++) {
            float lo = scb2[bi][2 * j].x * scale;
            float hi = scb2[bi][2 * j + 1].x * scale;
            h[j] = __floats2half2_rn(lo, hi);
        }
        uint4 v;
        v.x = *reinterpret_cast<uint32_t*>(&h[0]);
        v.y = *reinterpret_cast<uint32_t*>(&h[1]);
        v.z = *reinterpret_cast<uint32_t*>(&h[2]);
        v.w = *reinterpret_cast<uint32_t*>(&h[3]);
        int i = ibase + g * 8;
        size_t dst = rowbase + (size_t)(i >> 6) * KSB + tile_off(rr, (i & 63) * 2);
        *reinterpret_cast<uint4*>(g_wq + dst) = v;
    }
}

// ===========================================================================
// Kernel 2: GEMM  out = x @ wq^T + bias  (mma.sync fp16/f32)
//   128M x 256N x 64K block, 8 warps @ 64x64, 3-stage ring,
//   contiguous pre-swizzled loads + SOFTWARE-PIPELINED fragments.
// ===========================================================================
#define GBM 128
#define GBN 256
#define KTILES 32
#define A_ST 16384
#define B_ST 32768
#define STAGE (A_ST + B_ST)             // 49152
#define NSTG 3
#define GSMEM (NSTG * STAGE)            // 147456

__global__ __launch_bounds__(256, 1) void gemm_kernel(const float* __restrict__ bias,
                                                      float* __restrict__ out) {
    extern __shared__ char smem_raw[];
    uint32_t sb = (uint32_t)__cvta_generic_to_shared(smem_raw);

    int tid  = threadIdx.x;
    int lane = tid & 31;
    int wid  = tid >> 5;
    int bm0  = blockIdx.y * GBM;
    int bn0  = blockIdx.x * GBN;
    int wm   = (wid >> 2) * 64;
    int wn   = (wid & 3) * 64;

    // ---- contiguous loaders (pre-swizzled layout) ----
    const char* srcA = g_x  + (size_t)blockIdx.y * TILE_STR + (size_t)tid * 64;
    int bblk = (tid * 128) >> 14;
    int boff = (tid * 128) & 16383;
    const char* srcB = g_wq + (size_t)(blockIdx.x * 2 + bblk) * TILE_STR + boff;
    uint32_t dstA = (uint32_t)(tid * 64);
    uint32_t dstB = (uint32_t)(A_ST + tid * 128);

#define G_LOAD(slot, s)                                                       \
    do {                                                                      \
        uint32_t bse = sb + (uint32_t)(slot) * STAGE;                         \
        const char* pa = srcA + (size_t)(s) * KSB;                            \
        const char* pb = srcB + (size_t)(s) * KSB;                            \
        cp_async16(bse + dstA,      pa);                                      \
        cp_async16(bse + dstA + 16, pa + 16);                                 \
        cp_async16(bse + dstA + 32, pa + 32);                                 \
        cp_async16(bse + dstA + 48, pa + 48);                                 \
        cp_async16(bse + dstB,       pb);                                     \
        cp_async16(bse + dstB + 16,  pb + 16);                                \
        cp_async16(bse + dstB + 32,  pb + 32);                                \
        cp_async16(bse + dstB + 48,  pb + 48);                                \
        cp_async16(bse + dstB + 64,  pb + 64);                                \
        cp_async16(bse + dstB + 80,  pb + 80);                                \
        cp_async16(bse + dstB + 96,  pb + 96);                                \
        cp_async16(bse + dstB + 112, pb + 112);                               \
        asm volatile("cp.async.commit_group;" ::: "memory");                  \
    } while (0)

    // ---- ldmatrix per-lane bases ----
    uint32_t aRB[4], aXOR[4];
#pragma unroll
    for (int mi = 0; mi < 4; mi++) {
        int row = wm + mi * 16 + (lane & 15);
        aRB[mi]  = (uint32_t)(row * 128);
        aXOR[mi] = (uint32_t)((row & 7) << 4);
    }
    uint32_t aCH = (uint32_t)((lane >> 4) * 16);
    uint32_t bRB[4], bXOR[4];
#pragma unroll
    for (int p = 0; p < 4; p++) {
        int row = wn + (lane & 7) + ((lane >> 4) & 1) * 8 + p * 16;
        bRB[p]  = (uint32_t)(A_ST + (row >> 7) * KSB + (row & 127) * 128);
        bXOR[p] = (uint32_t)((row & 7) << 4);
    }
    uint32_t bCH = (uint32_t)(((lane >> 3) & 1) * 16);

    // double-buffered fragments
    uint32_t af[2][4][4];
    uint32_t bf[2][4][4];   // bf[buf][p][0..3] = two n8 tiles per p

#define LDFRAGS(stg, kb, bi)                                                  \
    do {                                                                      \
        _Pragma("unroll")                                                     \
        for (int mi = 0; mi < 4; mi++)                                        \
            ldsm_x4((stg) + aRB[mi] + (((kb) + aCH) ^ aXOR[mi]), af[bi][mi]); \
        _Pragma("unroll")                                                     \
        for (int p = 0; p < 4; p++)                                           \
            ldsm_x4((stg) + bRB[p] + (((kb) + bCH) ^ bXOR[p]), bf[bi][p]);    \
    } while (0)

#define DO_MMA(bi)                                                            \
    do {                                                                      \
        _Pragma("unroll")                                                     \
        for (int mi = 0; mi < 4; mi++)                                        \
            _Pragma("unroll")                                                 \
            for (int ni = 0; ni < 8; ni++) {                                  \
                asm volatile(                                                 \
                    "mma.sync.aligned.m16n8k16.row.col.f32.f16.f16.f32 "      \
                    "{%0,%1,%2,%3}, {%4,%5,%6,%7}, {%8,%9}, {%0,%1,%2,%3};"   \
                    : "+f"(acc[mi][ni][0]), "+f"(acc[mi][ni][1]),             \
                      "+f"(acc[mi][ni][2]), "+f"(acc[mi][ni][3])              \
                    : "r"(af[bi][mi][0]), "r"(af[bi][mi][1]),                 \
                      "r"(af[bi][mi][2]), "r"(af[bi][mi][3]),                 \
                      "r"(bf[bi][ni >> 1][(ni & 1) * 2]),                     \
                      "r"(bf[bi][ni >> 1][(ni & 1) * 2 + 1]));                \
            }                                                                 \
    } while (0)

    float acc[4][8][4];
#pragma unroll
    for (int mi = 0; mi < 4; mi++)
#pragma unroll
        for (int ni = 0; ni < 8; ni++)
#pragma unroll
            for (int r = 0; r < 4; r++) acc[mi][ni][r] = 0.0f;

    // prologue: load stages 0,1; ready stage 0; preload ks0 frags
    G_LOAD(0, 0);
    G_LOAD(1, 1);
    asm volatile("cp.async.wait_group 1;" ::: "memory");
    __syncthreads();
    LDFRAGS(sb, 0u, 0);

    int slot = 0, wslot = 2;
    for (int kt = 0; kt < KTILES; kt++) {
        uint32_t stg = sb + (uint32_t)slot * STAGE;

        // ks = 0..2: prefetch next frags, then mma current
#pragma unroll
        for (int ks = 0; ks < 3; ks++) {
            LDFRAGS(stg, (uint32_t)((ks + 1) * 32), (ks + 1) & 1);
            DO_MMA(ks & 1);
        }

        // issue next stage load BEFORE the final mma so tensor drains into the wait
        if (kt + 2 < KTILES) {
            G_LOAD(wslot, kt + 2);
        } else {
            asm volatile("cp.async.commit_group;" ::: "memory");
        }
        DO_MMA(1);   // ks = 3 (buf 1)

        asm volatile("cp.async.wait_group 1;" ::: "memory");
        __syncthreads();
        slot  = (slot == 2)  ? 0 : slot + 1;
        wslot = (wslot == 2) ? 0 : wslot + 1;
        if (kt + 1 < KTILES) {
            uint32_t stg2 = sb + (uint32_t)slot * STAGE;
            LDFRAGS(stg2, 0u, 0);
        }
    }

    // epilogue: += bias, fp32 store
#pragma unroll
    for (int mi = 0; mi < 4; mi++) {
        int row = bm0 + wm + mi * 16 + (lane >> 2);
        float* o0 = out + (size_t)row * O_DIM;
        float* o1 = out + (size_t)(row + 8) * O_DIM;
#pragma unroll
        for (int ni = 0; ni < 8; ni++) {
            int col = bn0 + wn + ni * 8 + (lane & 3) * 2;
            float bv0 = bias[col];
            float bv1 = bias[col + 1];
            *reinterpret_cast<float2*>(o0 + col) =
                make_float2(acc[mi][ni][0] + bv0, acc[mi][ni][1] + bv1);
            *reinterpret_cast<float2*>(o1 + col) =
                make_float2(acc[mi][ni][2] + bv0, acc[mi][ni][3] + bv1);
        }
    }
}

// ===========================================================================
extern "C" void kernel_launch(void* const* d_in, const int* in_sizes, int n_in,
                              void* d_out, int out_size) {
    const float* x    = (const float*)d_in[0];
    const float* w    = (const float*)d_in[1];
    const float* cb   = (const float*)d_in[2];
    const float* rs   = (const float*)d_in[3];
    const float* bias = (const float*)d_in[4];
    float* out = (float*)d_out;

    static bool attr_done = false;
    if (!attr_done) {
        cudaFuncSetAttribute(gemm_kernel, cudaFuncAttributeMaxDynamicSharedMemorySize, GSMEM);
        attr_done = true;
    }

    prep_kernel<<<QBLOCKS + M_DIM * I_DIM / (256 * 8), 256>>>(x, w, cb, rs);
    dim3 grid(O_DIM / GBN, M_DIM / GBM);
    gemm_kernel<<<grid, 256, GSMEM>>>(bias, out);
}

// round 9
// speedup vs baseline: 2.0160x; 1.2989x over previous
#include <cuda_runtime.h>
#include <cuda_fp16.h>
#include <cstdint>

// Problem dims (fixed)
#define O_DIM 2048
#define I_DIM 2048
#define M_DIM 4096
#define KC    256
#define PQD   8

// Tiled-swizzled scratch layout:
//   [tile128][kstage(64 halves)][128 rows x 128 bytes, SW128-swizzled] = 16KB blocks
#define KSB      16384
#define TILE_STR (32 * KSB)

__device__ __align__(16) char g_wq[O_DIM * I_DIM * 2];  // fp16, tiled-swizzled
__device__ __align__(16) char g_x [M_DIM * I_DIM * 2];  // fp16, tiled-swizzled

__device__ __forceinline__ uint32_t tile_off(int r, int ch) {
    return (uint32_t)(r * 128 + (ch ^ ((r & 7) << 4)));
}
__device__ __forceinline__ uint64_t ffma2(uint64_t a, uint64_t b, uint64_t c) {
    uint64_t d;
    asm("fma.rn.f32x2 %0, %1, %2, %3;" : "=l"(d) : "l"(a), "l"(b), "l"(c));
    return d;
}
__device__ __forceinline__ uint64_t pack2(float lo, float hi) {
    uint64_t d; asm("mov.b64 %0, {%1, %2};" : "=l"(d) : "f"(lo), "f"(hi)); return d;
}
__device__ __forceinline__ void unpack2(uint64_t v, float& lo, float& hi) {
    asm("mov.b64 {%0, %1}, %2;" : "=f"(lo), "=f"(hi) : "l"(v));
}
__device__ __forceinline__ void ldsm_x4(uint32_t addr, uint32_t* r) {
    asm volatile("ldmatrix.sync.aligned.m8n8.x4.shared.b16 {%0,%1,%2,%3}, [%4];"
                 : "=r"(r[0]), "=r"(r[1]), "=r"(r[2]), "=r"(r[3]) : "r"(addr));
}
__device__ __forceinline__ void mbar_init(uint32_t a, uint32_t cnt) {
    asm volatile("mbarrier.init.shared.b64 [%0], %1;" :: "r"(a), "r"(cnt) : "memory");
}
__device__ __forceinline__ void mbar_expect_tx(uint32_t a, uint32_t tx) {
    asm volatile("mbarrier.arrive.expect_tx.shared.b64 _, [%0], %1;"
                 :: "r"(a), "r"(tx) : "memory");
}
__device__ __forceinline__ void mbar_wait(uint32_t a, uint32_t parity) {
    asm volatile(
        "{\n\t.reg .pred P;\n\t"
        "WAITLOOP_%=:\n\t"
        "mbarrier.try_wait.parity.acquire.cta.shared::cta.b64 P, [%0], %1, 0x989680;\n\t"
        "@!P bra WAITLOOP_%=;\n\t"
        "}\n"
        :: "r"(a), "r"(parity) : "memory");
}
__device__ __forceinline__ void bulk_g2s(uint32_t dst, const void* src, uint32_t bytes,
                                         uint32_t bar) {
    asm volatile(
        "cp.async.bulk.shared::cluster.global.mbarrier::complete_tx::bytes [%0], [%1], %2, [%3];"
        :: "r"(dst), "l"(src), "r"(bytes), "r"(bar) : "memory");
}

// ===========================================================================
// Kernel 1 (fused): blocks [0,512)    -> PQ quantize (f32x2, 4 groups/thread)
//                   blocks [512,4608) -> convert x fp32 -> fp16 tiled
// ===========================================================================
#define QBLOCKS 512

__global__ __launch_bounds__(256) void prep_kernel(const float* __restrict__ x,
                                                   const float* __restrict__ w,
                                                   const float* __restrict__ cb,
                                                   const float* __restrict__ rs) {
    int tid = threadIdx.x;
    if (blockIdx.x >= QBLOCKS) {
        // ---- convert x: 8 floats -> one 16B chunk in tiled layout ----
        int g = (blockIdx.x - QBLOCKS) * 256 + tid;
        int m = g >> 8;
        int i = (g & 255) * 8;
        size_t src = (size_t)m * I_DIM + i;
        float4 a = *reinterpret_cast<const float4*>(x + src);
        float4 b = *reinterpret_cast<const float4*>(x + src + 4);
        __half2 h0 = __floats2half2_rn(a.x, a.y);
        __half2 h1 = __floats2half2_rn(a.z, a.w);
        __half2 h2 = __floats2half2_rn(b.x, b.y);
        __half2 h3 = __floats2half2_rn(b.z, b.w);
        uint4 v;
        v.x = *reinterpret_cast<uint32_t*>(&h0);
        v.y = *reinterpret_cast<uint32_t*>(&h1);
        v.z = *reinterpret_cast<uint32_t*>(&h2);
        v.w = *reinterpret_cast<uint32_t*>(&h3);
        size_t dst = (size_t)(m >> 7) * TILE_STR + (size_t)(i >> 6) * KSB
                   + tile_off(m & 127, (i & 63) * 2);
        *reinterpret_cast<uint4*>(g_x + dst) = v;
        return;
    }

    // ---- quantize: 4 groups/thread, packed f32x2 scoring ----
    __shared__ __align__(16) float2 scb2[KC][10];
    {
        const float4* cb4 = reinterpret_cast<const float4*>(cb);
        float4 a = cb4[tid * 2];
        float4 b = cb4[tid * 2 + 1];
        float s = a.x * a.x;
        s = fmaf(a.y, a.y, s); s = fmaf(a.z, a.z, s); s = fmaf(a.w, a.w, s);
        s = fmaf(b.x, b.x, s); s = fmaf(b.y, b.y, s); s = fmaf(b.z, b.z, s); s = fmaf(b.w, b.w, s);
        float c2h = 0.5f * s;
        scb2[tid][0] = make_float2(a.x, a.x);
        scb2[tid][1] = make_float2(a.y, a.y);
        scb2[tid][2] = make_float2(a.z, a.z);
        scb2[tid][3] = make_float2(a.w, a.w);
        scb2[tid][4] = make_float2(b.x, b.x);
        scb2[tid][5] = make_float2(b.y, b.y);
        scb2[tid][6] = make_float2(b.z, b.z);
        scb2[tid][7] = make_float2(b.w, b.w);
        scb2[tid][8] = make_float2(c2h, c2h);
    }
    __syncthreads();

    uint32_t scb_s = (uint32_t)__cvta_generic_to_shared(&scb2[0][0]);

    int t4 = blockIdx.x * 256 + tid;
    int g0 = t4 * 4;
    float scale = rs[g0 >> 8];
    float inv = 1.0f / scale;

    float xv[32];
    {
        const float4* wp = reinterpret_cast<const float4*>(w + (size_t)g0 * PQD);
#pragma unroll
        for (int q = 0; q < 8; q++) {
            float4 v = wp[q];
            xv[q * 4 + 0] = v.x; xv[q * 4 + 1] = v.y;
            xv[q * 4 + 2] = v.z; xv[q * 4 + 3] = v.w;
        }
    }
    uint64_t P01[8], P23[8];
#pragma unroll
    for (int j = 0; j < 8; j++) {
        P01[j] = pack2(-(xv[j] * inv), -(xv[8 + j] * inv));
        P23[j] = pack2(-(xv[16 + j] * inv), -(xv[24 + j] * inv));
    }

    float b0 = 3.4e38f, b1 = 3.4e38f, b2 = 3.4e38f, b3 = 3.4e38f;
    int i0 = 0, i1 = 0, i2 = 0, i3 = 0;

#pragma unroll 4
    for (int k = 0; k < KC; k++) {
        uint32_t a = scb_s + (uint32_t)k * 80;
        uint64_t c0, c1, c2, c3, c4, c5, c6, c7, ch;
        asm("ld.shared.v2.u64 {%0,%1}, [%2];" : "=l"(c0), "=l"(c1) : "r"(a));
        asm("ld.shared.v2.u64 {%0,%1}, [%2];" : "=l"(c2), "=l"(c3) : "r"(a + 16));
        asm("ld.shared.v2.u64 {%0,%1}, [%2];" : "=l"(c4), "=l"(c5) : "r"(a + 32));
        asm("ld.shared.v2.u64 {%0,%1}, [%2];" : "=l"(c6), "=l"(c7) : "r"(a + 48));
        asm("ld.shared.b64 %0, [%1];" : "=l"(ch) : "r"(a + 64));
        uint64_t d01 = ch, d23 = ch;
        d01 = ffma2(P01[0], c0, d01); d23 = ffma2(P23[0], c0, d23);
        d01 = ffma2(P01[1], c1, d01); d23 = ffma2(P23[1], c1, d23);
        d01 = ffma2(P01[2], c2, d01); d23 = ffma2(P23[2], c2, d23);
        d01 = ffma2(P01[3], c3, d01); d23 = ffma2(P23[3], c3, d23);
        d01 = ffma2(P01[4], c4, d01); d23 = ffma2(P23[4], c4, d23);
        d01 = ffma2(P01[5], c5, d01); d23 = ffma2(P23[5], c5, d23);
        d01 = ffma2(P01[6], c6, d01); d23 = ffma2(P23[6], c6, d23);
        d01 = ffma2(P01[7], c7, d01); d23 = ffma2(P23[7], c7, d23);
        float s0, s1, s2, s3;
        unpack2(d01, s0, s1);
        unpack2(d23, s2, s3);
        if (s0 < b0) { b0 = s0; i0 = k; }
        if (s1 < b1) { b1 = s1; i1 = k; }
        if (s2 < b2) { b2 = s2; i2 = k; }
        if (s3 < b3) { b3 = s3; i3 = k; }
    }

    int idxs[4] = {i0, i1, i2, i3};
    int o = g0 >> 8;
    int ibase = (g0 & 255) * 8;
    size_t rowbase = (size_t)(o >> 7) * TILE_STR;
    int rr = o & 127;
#pragma unroll
    for (int g = 0; g < 4; g++) {
        int bi = idxs[g];
        __half2 h[4];
#pragma unroll
        for (int j = 0; j < 4; j++) {
            float lo = scb2[bi][2 * j].x * scale;
            float hi = scb2[bi][2 * j + 1].x * scale;
            h[j] = __floats2half2_rn(lo, hi);
        }
        uint4 v;
        v.x = *reinterpret_cast<uint32_t*>(&h[0]);
        v.y = *reinterpret_cast<uint32_t*>(&h[1]);
        v.z = *reinterpret_cast<uint32_t*>(&h[2]);
        v.w = *reinterpret_cast<uint32_t*>(&h[3]);
        int i = ibase + g * 8;
        size_t dst = rowbase + (size_t)(i >> 6) * KSB + tile_off(rr, (i & 63) * 2);
        *reinterpret_cast<uint4*>(g_wq + dst) = v;
    }
}

// ===========================================================================
// Kernel 2: GEMM  out = x @ wq^T + bias  (mma.sync fp16/f32)
//   128M x 256N x 64K block, 8 warps @ 64x64, 3-stage ring fed by
//   cp.async.bulk (1 issue per stage buffer) + mbarrier complete_tx.
// ===========================================================================
#define GBM 128
#define GBN 256
#define KTILES 32
#define A_ST 16384
#define B_ST 32768
#define STAGE (A_ST + B_ST)             // 49152
#define NSTG 3
#define BAR_OFF (NSTG * STAGE)          // 147456
#define GSMEM (BAR_OFF + 64)

__global__ __launch_bounds__(256, 1) void gemm_kernel(const float* __restrict__ bias,
                                                      float* __restrict__ out) {
    extern __shared__ char smem_raw[];
    uint32_t sb = (uint32_t)__cvta_generic_to_shared(smem_raw);

    int tid  = threadIdx.x;
    int lane = tid & 31;
    int wid  = tid >> 5;
    int bm0  = blockIdx.y * GBM;
    int bn0  = blockIdx.x * GBN;
    int wm   = (wid >> 2) * 64;
    int wn   = (wid & 3) * 64;

    const char* srcA = g_x  + (size_t)blockIdx.y * TILE_STR;          // 16KB / stage
    const char* srcB = g_wq + (size_t)(blockIdx.x * 2) * TILE_STR;    // 2 x 16KB / stage

    // ---- mbarrier init + prologue bulk loads (3 stages) ----
    if (tid == 0) {
#pragma unroll
        for (int s = 0; s < NSTG; s++) mbar_init(sb + BAR_OFF + s * 8, 1);
        asm volatile("fence.proxy.async.shared::cta;" ::: "memory");
#pragma unroll
        for (int s = 0; s < NSTG; s++) {
            uint32_t bar = sb + BAR_OFF + s * 8;
            uint32_t dst = sb + (uint32_t)s * STAGE;
            mbar_expect_tx(bar, STAGE);
            bulk_g2s(dst, srcA + (size_t)s * KSB, A_ST, bar);
            bulk_g2s(dst + A_ST, srcB + (size_t)s * KSB, B_ST / 2, bar);
            bulk_g2s(dst + A_ST + B_ST / 2, srcB + TILE_STR + (size_t)s * KSB, B_ST / 2, bar);
        }
    }
    __syncthreads();

    // ---- ldmatrix per-lane bases ----
    uint32_t aRB[4], aXOR[4];
#pragma unroll
    for (int mi = 0; mi < 4; mi++) {
        int row = wm + mi * 16 + (lane & 15);
        aRB[mi]  = (uint32_t)(row * 128);
        aXOR[mi] = (uint32_t)((row & 7) << 4);
    }
    uint32_t aCH = (uint32_t)((lane >> 4) * 16);
    uint32_t bRB[4], bXOR[4];
#pragma unroll
    for (int p = 0; p < 4; p++) {
        int row = wn + (lane & 7) + ((lane >> 4) & 1) * 8 + p * 16;
        bRB[p]  = (uint32_t)(A_ST + (row >> 7) * KSB + (row & 127) * 128);
        bXOR[p] = (uint32_t)((row & 7) << 4);
    }
    uint32_t bCH = (uint32_t)(((lane >> 3) & 1) * 16);

    uint32_t af[2][4][4];
    uint32_t bf[2][4][4];

#define LDFRAGS(stg, kb, bi)                                                  \
    do {                                                                      \
        _Pragma("unroll")                                                     \
        for (int mi = 0; mi < 4; mi++)                                        \
            ldsm_x4((stg) + aRB[mi] + (((kb) + aCH) ^ aXOR[mi]), af[bi][mi]); \
        _Pragma("unroll")                                                     \
        for (int p = 0; p < 4; p++)                                           \
            ldsm_x4((stg) + bRB[p] + (((kb) + bCH) ^ bXOR[p]), bf[bi][p]);    \
    } while (0)

#define DO_MMA(bi)                                                            \
    do {                                                                      \
        _Pragma("unroll")                                                     \
        for (int mi = 0; mi < 4; mi++)                                        \
            _Pragma("unroll")                                                 \
            for (int ni = 0; ni < 8; ni++) {                                  \
                asm volatile(                                                 \
                    "mma.sync.aligned.m16n8k16.row.col.f32.f16.f16.f32 "      \
                    "{%0,%1,%2,%3}, {%4,%5,%6,%7}, {%8,%9}, {%0,%1,%2,%3};"   \
                    : "+f"(acc[mi][ni][0]), "+f"(acc[mi][ni][1]),             \
                      "+f"(acc[mi][ni][2]), "+f"(acc[mi][ni][3])              \
                    : "r"(af[bi][mi][0]), "r"(af[bi][mi][1]),                 \
                      "r"(af[bi][mi][2]), "r"(af[bi][mi][3]),                 \
                      "r"(bf[bi][ni >> 1][(ni & 1) * 2]),                     \
                      "r"(bf[bi][ni >> 1][(ni & 1) * 2 + 1]));                \
            }                                                                 \
    } while (0)

    float acc[4][8][4];
#pragma unroll
    for (int mi = 0; mi < 4; mi++)
#pragma unroll
        for (int ni = 0; ni < 8; ni++)
#pragma unroll
            for (int r = 0; r < 4; r++) acc[mi][ni][r] = 0.0f;

    int slot = 0;
    for (int kt = 0; kt < KTILES; kt++) {
        uint32_t bar = sb + BAR_OFF + slot * 8;
        mbar_wait(bar, (uint32_t)((kt / NSTG) & 1));

        uint32_t stg = sb + (uint32_t)slot * STAGE;
        LDFRAGS(stg, 0u, 0);
#pragma unroll
        for (int ks = 0; ks < 3; ks++) {
            LDFRAGS(stg, (uint32_t)((ks + 1) * 32), (ks + 1) & 1);
            DO_MMA(ks & 1);
        }
        DO_MMA(1);

        __syncthreads();   // all warps done reading this slot
        if (kt + NSTG < KTILES && tid == 0) {
            int s = kt + NSTG;
            mbar_expect_tx(bar, STAGE);
            bulk_g2s(stg, srcA + (size_t)s * KSB, A_ST, bar);
            bulk_g2s(stg + A_ST, srcB + (size_t)s * KSB, B_ST / 2, bar);
            bulk_g2s(stg + A_ST + B_ST / 2, srcB + TILE_STR + (size_t)s * KSB, B_ST / 2, bar);
        }
        slot = (slot == NSTG - 1) ? 0 : slot + 1;
    }

    // epilogue: += bias, fp32 store
#pragma unroll
    for (int mi = 0; mi < 4; mi++) {
        int row = bm0 + wm + mi * 16 + (lane >> 2);
        float* o0 = out + (size_t)row * O_DIM;
        float* o1 = out + (size_t)(row + 8) * O_DIM;
#pragma unroll
        for (int ni = 0; ni < 8; ni++) {
            int col = bn0 + wn + ni * 8 + (lane & 3) * 2;
            float bv0 = bias[col];
            float bv1 = bias[col + 1];
            *reinterpret_cast<float2*>(o0 + col) =
                make_float2(acc[mi][ni][0] + bv0, acc[mi][ni][1] + bv1);
            *reinterpret_cast<float2*>(o1 + col) =
                make_float2(acc[mi][ni][2] + bv0, acc[mi][ni][3] + bv1);
        }
    }
}

// ===========================================================================
extern "C" void kernel_launch(void* const* d_in, const int* in_sizes, int n_in,
                              void* d_out, int out_size) {
    const float* x    = (const float*)d_in[0];
    const float* w    = (const float*)d_in[1];
    const float* cb   = (const float*)d_in[2];
    const float* rs   = (const float*)d_in[3];
    const float* bias = (const float*)d_in[4];
    float* out = (float*)d_out;

    static bool attr_done = false;
    if (!attr_done) {
        cudaFuncSetAttribute(gemm_kernel, cudaFuncAttributeMaxDynamicSharedMemorySize, GSMEM);
        attr_done = true;
    }

    prep_kernel<<<QBLOCKS + M_DIM * I_DIM / (256 * 8), 256>>>(x, w, cb, rs);
    dim3 grid(O_DIM / GBN, M_DIM / GBM);
    gemm_kernel<<<grid, 256, GSMEM>>>(bias, out);
}

// round 10
// speedup vs baseline: 2.0981x; 1.0407x over previous
#include <cuda_runtime.h>
#include <cuda_fp16.h>
#include <cstdint>

// Problem dims (fixed)
#define O_DIM 2048
#define I_DIM 2048
#define M_DIM 4096
#define KC    256
#define PQD   8

// Tiled-swizzled scratch layout:
//   [tile128][kstage(64 halves)][128 rows x 128 bytes, SW128-swizzled] = 16KB blocks
#define KSB      16384
#define TILE_STR (32 * KSB)

__device__ __align__(16) char g_wq[O_DIM * I_DIM * 2];  // fp16, tiled-swizzled
__device__ __align__(16) char g_x [M_DIM * I_DIM * 2];  // fp16, tiled-swizzled

__device__ __forceinline__ uint32_t tile_off(int r, int ch) {
    return (uint32_t)(r * 128 + (ch ^ ((r & 7) << 4)));
}
__device__ __forceinline__ uint64_t ffma2(uint64_t a, uint64_t b, uint64_t c) {
    uint64_t d;
    asm("fma.rn.f32x2 %0, %1, %2, %3;" : "=l"(d) : "l"(a), "l"(b), "l"(c));
    return d;
}
__device__ __forceinline__ uint64_t pack2(float lo, float hi) {
    uint64_t d; asm("mov.b64 %0, {%1, %2};" : "=l"(d) : "f"(lo), "f"(hi)); return d;
}
__device__ __forceinline__ void unpack2(uint64_t v, float& lo, float& hi) {
    asm("mov.b64 {%0, %1}, %2;" : "=f"(lo), "=f"(hi) : "l"(v));
}
__device__ __forceinline__ void ldsm_x4(uint32_t addr, uint32_t* r) {
    asm volatile("ldmatrix.sync.aligned.m8n8.x4.shared.b16 {%0,%1,%2,%3}, [%4];"
                 : "=r"(r[0]), "=r"(r[1]), "=r"(r[2]), "=r"(r[3]) : "r"(addr));
}
__device__ __forceinline__ void mbar_init(uint32_t a, uint32_t cnt) {
    asm volatile("mbarrier.init.shared.b64 [%0], %1;" :: "r"(a), "r"(cnt) : "memory");
}
__device__ __forceinline__ void mbar_expect_tx(uint32_t a, uint32_t tx) {
    asm volatile("mbarrier.arrive.expect_tx.shared.b64 _, [%0], %1;"
                 :: "r"(a), "r"(tx) : "memory");
}
__device__ __forceinline__ void mbar_wait(uint32_t a, uint32_t parity) {
    asm volatile(
        "{\n\t.reg .pred P;\n\t"
        "WAITLOOP_%=:\n\t"
        "mbarrier.try_wait.parity.acquire.cta.shared::cta.b64 P, [%0], %1, 0x989680;\n\t"
        "@!P bra WAITLOOP_%=;\n\t"
        "}\n"
        :: "r"(a), "r"(parity) : "memory");
}
__device__ __forceinline__ void bulk_g2s(uint32_t dst, const void* src, uint32_t bytes,
                                         uint32_t bar) {
    asm volatile(
        "cp.async.bulk.shared::cluster.global.mbarrier::complete_tx::bytes [%0], [%1], %2, [%3];"
        :: "r"(dst), "l"(src), "r"(bytes), "r"(bar) : "memory");
}

// ===========================================================================
// Kernel 1 (fused): blocks [0,512)    -> PQ quantize (f32x2, 4 groups/thread)
//                   blocks [512,4608) -> convert x fp32 -> fp16 tiled
// ===========================================================================
#define QBLOCKS 512

__global__ __launch_bounds__(256) void prep_kernel(const float* __restrict__ x,
                                                   const float* __restrict__ w,
                                                   const float* __restrict__ cb,
                                                   const float* __restrict__ rs) {
    int tid = threadIdx.x;
    if (blockIdx.x >= QBLOCKS) {
        int g = (blockIdx.x - QBLOCKS) * 256 + tid;
        int m = g >> 8;
        int i = (g & 255) * 8;
        size_t src = (size_t)m * I_DIM + i;
        float4 a = *reinterpret_cast<const float4*>(x + src);
        float4 b = *reinterpret_cast<const float4*>(x + src + 4);
        __half2 h0 = __floats2half2_rn(a.x, a.y);
        __half2 h1 = __floats2half2_rn(a.z, a.w);
        __half2 h2 = __floats2half2_rn(b.x, b.y);
        __half2 h3 = __floats2half2_rn(b.z, b.w);
        uint4 v;
        v.x = *reinterpret_cast<uint32_t*>(&h0);
        v.y = *reinterpret_cast<uint32_t*>(&h1);
        v.z = *reinterpret_cast<uint32_t*>(&h2);
        v.w = *reinterpret_cast<uint32_t*>(&h3);
        size_t dst = (size_t)(m >> 7) * TILE_STR + (size_t)(i >> 6) * KSB
                   + tile_off(m & 127, (i & 63) * 2);
        *reinterpret_cast<uint4*>(g_x + dst) = v;
        return;
    }

    __shared__ __align__(16) float2 scb2[KC][10];
    {
        const float4* cb4 = reinterpret_cast<const float4*>(cb);
        float4 a = cb4[tid * 2];
        float4 b = cb4[tid * 2 + 1];
        float s = a.x * a.x;
        s = fmaf(a.y, a.y, s); s = fmaf(a.z, a.z, s); s = fmaf(a.w, a.w, s);
        s = fmaf(b.x, b.x, s); s = fmaf(b.y, b.y, s); s = fmaf(b.z, b.z, s); s = fmaf(b.w, b.w, s);
        float c2h = 0.5f * s;
        scb2[tid][0] = make_float2(a.x, a.x);
        scb2[tid][1] = make_float2(a.y, a.y);
        scb2[tid][2] = make_float2(a.z, a.z);
        scb2[tid][3] = make_float2(a.w, a.w);
        scb2[tid][4] = make_float2(b.x, b.x);
        scb2[tid][5] = make_float2(b.y, b.y);
        scb2[tid][6] = make_float2(b.z, b.z);
        scb2[tid][7] = make_float2(b.w, b.w);
        scb2[tid][8] = make_float2(c2h, c2h);
    }
    __syncthreads();

    uint32_t scb_s = (uint32_t)__cvta_generic_to_shared(&scb2[0][0]);

    int t4 = blockIdx.x * 256 + tid;
    int g0 = t4 * 4;
    float scale = rs[g0 >> 8];
    float inv = 1.0f / scale;

    float xv[32];
    {
        const float4* wp = reinterpret_cast<const float4*>(w + (size_t)g0 * PQD);
#pragma unroll
        for (int q = 0; q < 8; q++) {
            float4 v = wp[q];
            xv[q * 4 + 0] = v.x; xv[q * 4 + 1] = v.y;
            xv[q * 4 + 2] = v.z; xv[q * 4 + 3] = v.w;
        }
    }
    uint64_t P01[8], P23[8];
#pragma unroll
    for (int j = 0; j < 8; j++) {
        P01[j] = pack2(-(xv[j] * inv), -(xv[8 + j] * inv));
        P23[j] = pack2(-(xv[16 + j] * inv), -(xv[24 + j] * inv));
    }

    float b0 = 3.4e38f, b1 = 3.4e38f, b2 = 3.4e38f, b3 = 3.4e38f;
    int i0 = 0, i1 = 0, i2 = 0, i3 = 0;

#pragma unroll 4
    for (int k = 0; k < KC; k++) {
        uint32_t a = scb_s + (uint32_t)k * 80;
        uint64_t c0, c1, c2, c3, c4, c5, c6, c7, ch;
        asm("ld.shared.v2.u64 {%0,%1}, [%2];" : "=l"(c0), "=l"(c1) : "r"(a));
        asm("ld.shared.v2.u64 {%0,%1}, [%2];" : "=l"(c2), "=l"(c3) : "r"(a + 16));
        asm("ld.shared.v2.u64 {%0,%1}, [%2];" : "=l"(c4), "=l"(c5) : "r"(a + 32));
        asm("ld.shared.v2.u64 {%0,%1}, [%2];" : "=l"(c6), "=l"(c7) : "r"(a + 48));
        asm("ld.shared.b64 %0, [%1];" : "=l"(ch) : "r"(a + 64));
        uint64_t d01 = ch, d23 = ch;
        d01 = ffma2(P01[0], c0, d01); d23 = ffma2(P23[0], c0, d23);
        d01 = ffma2(P01[1], c1, d01); d23 = ffma2(P23[1], c1, d23);
        d01 = ffma2(P01[2], c2, d01); d23 = ffma2(P23[2], c2, d23);
        d01 = ffma2(P01[3], c3, d01); d23 = ffma2(P23[3], c3, d23);
        d01 = ffma2(P01[4], c4, d01); d23 = ffma2(P23[4], c4, d23);
        d01 = ffma2(P01[5], c5, d01); d23 = ffma2(P23[5], c5, d23);
        d01 = ffma2(P01[6], c6, d01); d23 = ffma2(P23[6], c6, d23);
        d01 = ffma2(P01[7], c7, d01); d23 = ffma2(P23[7], c7, d23);
        float s0, s1, s2, s3;
        unpack2(d01, s0, s1);
        unpack2(d23, s2, s3);
        if (s0 < b0) { b0 = s0; i0 = k; }
        if (s1 < b1) { b1 = s1; i1 = k; }
        if (s2 < b2) { b2 = s2; i2 = k; }
        if (s3 < b3) { b3 = s3; i3 = k; }
    }

    int idxs[4] = {i0, i1, i2, i3};
    int o = g0 >> 8;
    int ibase = (g0 & 255) * 8;
    size_t rowbase = (size_t)(o >> 7) * TILE_STR;
    int rr = o & 127;
#pragma unroll
    for (int g = 0; g < 4; g++) {
        int bi = idxs[g];
        __half2 h[4];
#pragma unroll
        for (int j = 0; j < 4; j++) {
            float lo = scb2[bi][2 * j].x * scale;
            float hi = scb2[bi][2 * j + 1].x * scale;
            h[j] = __floats2half2_rn(lo, hi);
        }
        uint4 v;
        v.x = *reinterpret_cast<uint32_t*>(&h[0]);
        v.y = *reinterpret_cast<uint32_t*>(&h[1]);
        v.z = *reinterpret_cast<uint32_t*>(&h[2]);
        v.w = *reinterpret_cast<uint32_t*>(&h[3]);
        int i = ibase + g * 8;
        size_t dst = rowbase + (size_t)(i >> 6) * KSB + tile_off(rr, (i & 63) * 2);
        *reinterpret_cast<uint4*>(g_wq + dst) = v;
    }
}

// ===========================================================================
// Kernel 2: GEMM  out = x @ wq^T + bias  (mma.sync fp16/f32)
//   128M x 128N x 64K block, 8 warps @ 32x64, 3-stage bulk ring,
//   2 CTAs/SM (16 warps/SM to fill the HMMA pipe through tile edges).
// ===========================================================================
#define GBM 128
#define GBN 128
#define KTILES 32
#define A_ST 16384
#define B_ST 16384
#define STAGE (A_ST + B_ST)             // 32768
#define NSTG 3
#define BAR_OFF (NSTG * STAGE)          // 98304
#define GSMEM (BAR_OFF + 64)

__global__ __launch_bounds__(256, 2) void gemm_kernel(const float* __restrict__ bias,
                                                      float* __restrict__ out) {
    extern __shared__ char smem_raw[];
    uint32_t sb = (uint32_t)__cvta_generic_to_shared(smem_raw);

    int tid  = threadIdx.x;
    int lane = tid & 31;
    int wid  = tid >> 5;
    int bm0  = blockIdx.y * GBM;
    int bn0  = blockIdx.x * GBN;
    int wm   = (wid >> 1) * 32;      // 4 warps in M
    int wn   = (wid & 1) * 64;       // 2 warps in N

    const char* srcA = g_x  + (size_t)blockIdx.y * TILE_STR;   // 16KB / stage
    const char* srcB = g_wq + (size_t)blockIdx.x * TILE_STR;   // 16KB / stage

    if (tid == 0) {
#pragma unroll
        for (int s = 0; s < NSTG; s++) mbar_init(sb + BAR_OFF + s * 8, 1);
        asm volatile("fence.proxy.async.shared::cta;" ::: "memory");
#pragma unroll
        for (int s = 0; s < NSTG; s++) {
            uint32_t bar = sb + BAR_OFF + s * 8;
            uint32_t dst = sb + (uint32_t)s * STAGE;
            mbar_expect_tx(bar, STAGE);
            bulk_g2s(dst, srcA + (size_t)s * KSB, A_ST, bar);
            bulk_g2s(dst + A_ST, srcB + (size_t)s * KSB, B_ST, bar);
        }
    }
    __syncthreads();

    // ---- ldmatrix per-lane bases ----
    uint32_t aRB[2], aXOR[2];
#pragma unroll
    for (int mi = 0; mi < 2; mi++) {
        int row = wm + mi * 16 + (lane & 15);
        aRB[mi]  = (uint32_t)(row * 128);
        aXOR[mi] = (uint32_t)((row & 7) << 4);
    }
    uint32_t aCH = (uint32_t)((lane >> 4) * 16);
    uint32_t bRB[4], bXOR[4];
#pragma unroll
    for (int p = 0; p < 4; p++) {
        int row = wn + (lane & 7) + ((lane >> 4) & 1) * 8 + p * 16;
        bRB[p]  = (uint32_t)(A_ST + row * 128);
        bXOR[p] = (uint32_t)((row & 7) << 4);
    }
    uint32_t bCH = (uint32_t)(((lane >> 3) & 1) * 16);

    uint32_t af[2][2][4];
    uint32_t bf[2][4][4];

#define LDFRAGS(stg, kb, bi)                                                  \
    do {                                                                      \
        _Pragma("unroll")                                                     \
        for (int mi = 0; mi < 2; mi++)                                        \
            ldsm_x4((stg) + aRB[mi] + (((kb) + aCH) ^ aXOR[mi]), af[bi][mi]); \
        _Pragma("unroll")                                                     \
        for (int p = 0; p < 4; p++)                                           \
            ldsm_x4((stg) + bRB[p] + (((kb) + bCH) ^ bXOR[p]), bf[bi][p]);    \
    } while (0)

#define DO_MMA(bi)                                                            \
    do {                                                                      \
        _Pragma("unroll")                                                     \
        for (int mi = 0; mi < 2; mi++)                                        \
            _Pragma("unroll")                                                 \
            for (int ni = 0; ni < 8; ni++) {                                  \
                asm volatile(                                                 \
                    "mma.sync.aligned.m16n8k16.row.col.f32.f16.f16.f32 "      \
                    "{%0,%1,%2,%3}, {%4,%5,%6,%7}, {%8,%9}, {%0,%1,%2,%3};"   \
                    : "+f"(acc[mi][ni][0]), "+f"(acc[mi][ni][1]),             \
                      "+f"(acc[mi][ni][2]), "+f"(acc[mi][ni][3])              \
                    : "r"(af[bi][mi][0]), "r"(af[bi][mi][1]),                 \
                      "r"(af[bi][mi][2]), "r"(af[bi][mi][3]),                 \
                      "r"(bf[bi][ni >> 1][(ni & 1) * 2]),                     \
                      "r"(bf[bi][ni >> 1][(ni & 1) * 2 + 1]));                \
            }                                                                 \
    } while (0)

    float acc[2][8][4];
#pragma unroll
    for (int mi = 0; mi < 2; mi++)
#pragma unroll
        for (int ni = 0; ni < 8; ni++)
#pragma unroll
            for (int r = 0; r < 4; r++) acc[mi][ni][r] = 0.0f;

    int slot = 0;
    for (int kt = 0; kt < KTILES; kt++) {
        uint32_t bar = sb + BAR_OFF + slot * 8;
        mbar_wait(bar, (uint32_t)((kt / NSTG) & 1));

        uint32_t stg = sb + (uint32_t)slot * STAGE;
        LDFRAGS(stg, 0u, 0);
#pragma unroll
        for (int ks = 0; ks < 3; ks++) {
            LDFRAGS(stg, (uint32_t)((ks + 1) * 32), (ks + 1) & 1);
            DO_MMA(ks & 1);
        }
        DO_MMA(1);

        __syncthreads();   // all warps done reading this slot
        if (kt + NSTG < KTILES && tid == 0) {
            int s = kt + NSTG;
            mbar_expect_tx(bar, STAGE);
            bulk_g2s(stg, srcA + (size_t)s * KSB, A_ST, bar);
            bulk_g2s(stg + A_ST, srcB + (size_t)s * KSB, B_ST, bar);
        }
        slot = (slot == NSTG - 1) ? 0 : slot + 1;
    }

    // epilogue: += bias, fp32 store
#pragma unroll
    for (int mi = 0; mi < 2; mi++) {
        int row = bm0 + wm + mi * 16 + (lane >> 2);
        float* o0 = out + (size_t)row * O_DIM;
        float* o1 = out + (size_t)(row + 8) * O_DIM;
#pragma unroll
        for (int ni = 0; ni < 8; ni++) {
            int col = bn0 + wn + ni * 8 + (lane & 3) * 2;
            float bv0 = bias[col];
            float bv1 = bias[col + 1];
            *reinterpret_cast<float2*>(o0 + col) =
                make_float2(acc[mi][ni][0] + bv0, acc[mi][ni][1] + bv1);
            *reinterpret_cast<float2*>(o1 + col) =
                make_float2(acc[mi][ni][2] + bv0, acc[mi][ni][3] + bv1);
        }
    }
}

// ===========================================================================
extern "C" void kernel_launch(void* const* d_in, const int* in_sizes, int n_in,
                              void* d_out, int out_size) {
    const float* x    = (const float*)d_in[0];
    const float* w    = (const float*)d_in[1];
    const float* cb   = (const float*)d_in[2];
    const float* rs   = (const float*)d_in[3];
    const float* bias = (const float*)d_in[4];
    float* out = (float*)d_out;

    static bool attr_done = false;
    if (!attr_done) {
        cudaFuncSetAttribute(gemm_kernel, cudaFuncAttributeMaxDynamicSharedMemorySize, GSMEM);
        attr_done = true;
    }

    prep_kernel<<<QBLOCKS + M_DIM * I_DIM / (256 * 8), 256>>>(x, w, cb, rs);
    dim3 grid(O_DIM / GBN, M_DIM / GBM);
    gemm_kernel<<<grid, 256, GSMEM>>>(bias, out);
}